// round 8
// baseline (speedup 1.0000x reference)
#include <cuda_runtime.h>
#include <cuda_bf16.h>
#include <stdint.h>
#include <math.h>

#define MAXL   20000
#define NACT   48
#define FD     64
#define IND    2048
#define NFR    32
#define NSMP   3
#define NBLK   5
#define SCHUNK 16

// ---------------- scratch (device globals; no allocation) ----------------
__device__ float g_spart[SCHUNK * MAXL];    // partial scores per d-chunk
__device__ float g_w[MAXL];                 // softmax weights
__device__ int   g_S;
__device__ int   g_start[NACT], g_len[NACT], g_pred[NACT], g_val2seg[NACT];
__device__ int   g_samp[NSMP * NFR];
__device__ float g_qk[NACT * IND];          // (Wk^T q_pred[s]) / 8
__device__ float g_xsum[NACT * IND];        // sum_l w_l x_l per segment
__device__ float g_hl[NACT * 2 * FD];       // [seg_feat | label_emb]
__device__ float g_tow[NSMP * FD];          // conv tower output per sample
__device__ float g_gi[2 * NACT * 3 * FD];   // input-side GRU gates
__device__ float g_h[NACT * 2 * FD];        // [h_fwd | h_bwd]
__device__ float g_rp[NACT * NACT];         // refine_pred

// ---------------- helpers ----------------
__device__ __forceinline__ float warpSum(float v) {
#pragma unroll
    for (int o = 16; o; o >>= 1) v += __shfl_xor_sync(0xffffffffu, v, o);
    return v;
}
__device__ __forceinline__ float warpMax(float v) {
#pragma unroll
    for (int o = 16; o; o >>= 1) v = fmaxf(v, __shfl_xor_sync(0xffffffffu, v, o));
    return v;
}
__device__ __forceinline__ float leaky(float x) { return x >= 0.f ? x : 0.1f * x; }
__device__ __forceinline__ float sigm(float x)  { return 1.f / (1.f + expf(-x)); }
__device__ __forceinline__ uint32_t rotl32(uint32_t x, int r) { return (x << r) | (x >> (32 - r)); }

// Threefry-2x32-20 (jax-exact)
__device__ uint2 tf2x32(uint32_t k0, uint32_t k1, uint32_t x0, uint32_t x1) {
    uint32_t ks2 = k0 ^ k1 ^ 0x1BD11BDAu;
    x0 += k0; x1 += k1;
    x0 += x1; x1 = rotl32(x1, 13); x1 ^= x0;
    x0 += x1; x1 = rotl32(x1, 15); x1 ^= x0;
    x0 += x1; x1 = rotl32(x1, 26); x1 ^= x0;
    x0 += x1; x1 = rotl32(x1, 6);  x1 ^= x0;
    x0 += k1; x1 += ks2 + 1u;
    x0 += x1; x1 = rotl32(x1, 17); x1 ^= x0;
    x0 += x1; x1 = rotl32(x1, 29); x1 ^= x0;
    x0 += x1; x1 = rotl32(x1, 16); x1 ^= x0;
    x0 += x1; x1 = rotl32(x1, 24); x1 ^= x0;
    x0 += ks2; x1 += k0 + 2u;
    x0 += x1; x1 = rotl32(x1, 13); x1 ^= x0;
    x0 += x1; x1 = rotl32(x1, 15); x1 ^= x0;
    x0 += x1; x1 = rotl32(x1, 26); x1 ^= x0;
    x0 += x1; x1 = rotl32(x1, 6);  x1 ^= x0;
    x0 += k0; x1 += k1 + 3u;
    x0 += x1; x1 = rotl32(x1, 17); x1 ^= x0;
    x0 += x1; x1 = rotl32(x1, 29); x1 ^= x0;
    x0 += x1; x1 = rotl32(x1, 16); x1 ^= x0;
    x0 += x1; x1 = rotl32(x1, 24); x1 ^= x0;
    x0 += k1; x1 += ks2 + 4u;
    x0 += x1; x1 = rotl32(x1, 13); x1 ^= x0;
    x0 += x1; x1 = rotl32(x1, 15); x1 ^= x0;
    x0 += x1; x1 = rotl32(x1, 26); x1 ^= x0;
    x0 += x1; x1 = rotl32(x1, 6);  x1 ^= x0;
    x0 += ks2; x1 += k0 + 5u;
    return make_uint2(x0, x1);
}

// ---------------- kernels ----------------

// Segments (sorted action_idx) + jax-PRNG sample indices, one tiny block.
__global__ void k_init(const int* __restrict__ a, int L) {
    __shared__ int lo_s[NACT + 1];
    __shared__ int S_s;
    __shared__ uint32_t bits[NACT];
    __shared__ int sel[NACT];
    __shared__ uint32_t sk0, sk1;
    int tid = threadIdx.x;
    if (tid <= NACT) {
        int lo = 0, hi = L;
        while (lo < hi) { int mid = (lo + hi) >> 1; if (a[mid] < tid) lo = mid + 1; else hi = mid; }
        lo_s[tid] = lo;
    }
    __syncthreads();
    if (tid == 0) {
        int s = 0;
        for (int vv = 0; vv < NACT; vv++) {
            int st = lo_s[vv], en = lo_s[vv + 1];
            if (en > st) { g_val2seg[vv] = s; g_start[s] = st; g_len[s] = en - st; g_pred[s] = vv; s++; }
            else g_val2seg[vv] = 0;
        }
        g_S = s; S_s = s;
    }
    __syncthreads();
    int S = S_s;
    for (int i = 0; i < NSMP; i++) {
        if (tid == 0) {
            uint2 fk  = tf2x32(0u, 42u, 0u, (uint32_t)i);   // fold_in(key(42), i)
            uint2 sub = tf2x32(fk.x, fk.y, 0u, 1u);          // split -> subkey
            sk0 = sub.x; sk1 = sub.y;
        }
        __syncthreads();
        if (tid < S) {
            uint2 o = tf2x32(sk0, sk1, 0u, (uint32_t)tid);   // partitionable random_bits
            bits[tid] = o.x ^ o.y;
        }
        __syncthreads();
        if (tid < S) {
            uint32_t kj = bits[tid];
            int rank = 0;
            for (int m = 0; m < S; m++) {
                uint32_t km = bits[m];
                rank += ((km < kj) || (km == kj && m < tid)) ? 1 : 0;
            }
            sel[tid] = (rank < NFR) ? 1 : 0;
        }
        __syncthreads();
        if (tid == 0) {
            int c = 0;
            for (int j = 0; j < S && c < NFR; j++)
                if (sel[j]) g_samp[i * NFR + c++] = j;
            while (c < NFR) { g_samp[i * NFR + c] = c % (S > 0 ? S : 1); c++; }
        }
        __syncthreads();
    }
}

// qk[s][d] = (1/8) * sum_f Wk[f][d] * query_emb[pred[s]][f]
__global__ void k_qk(const float* __restrict__ Wk, const float* __restrict__ qemb) {
    int s = blockIdx.y; if (s >= g_S) return;
    int d = blockIdx.x * 256 + threadIdx.x;
    const float* q = qemb + g_pred[s] * FD;
    float acc = 0.f;
#pragma unroll
    for (int f = 0; f < FD; f++) acc += Wk[(size_t)f * IND + d] * q[f];
    g_qk[s * IND + d] = acc * 0.125f;
}

// Pass 1 over X: each thread = 4 consecutive l (float4), 16 d-chunks of 128.
__global__ void k_score(const float* __restrict__ X, const int* __restrict__ a, int L) {
    int t = blockIdx.x * 256 + threadIdx.x;
    int nl4 = (L + 3) >> 2;
    if (t >= nl4) return;
    int l0 = t << 2;
    int c = blockIdx.y;
    int dbase = c * (IND / SCHUNK);            // 128 d's per chunk
    if (l0 + 3 < L) {
        int s0 = g_val2seg[a[l0]];
        int s3 = g_val2seg[a[l0 + 3]];
        if (s0 == s3) {
            const float* qr = g_qk + s0 * IND + dbase;
            const float* Xb = X + (size_t)dbase * L + l0;
            float a0 = 0.f, a1 = 0.f, a2 = 0.f, a3 = 0.f;
#pragma unroll 4
            for (int d = 0; d < IND / SCHUNK; d++) {
                float4 x4 = *(const float4*)(Xb + (size_t)d * L);
                float q = qr[d];
                a0 += x4.x * q; a1 += x4.y * q; a2 += x4.z * q; a3 += x4.w * q;
            }
            *(float4*)(g_spart + (size_t)c * L + l0) = make_float4(a0, a1, a2, a3);
            return;
        }
    }
    // tail / segment-boundary fallback (rare)
    for (int j = 0; j < 4 && l0 + j < L; j++) {
        int s = g_val2seg[a[l0 + j]];
        const float* qr = g_qk + s * IND + dbase;
        const float* Xp = X + (size_t)dbase * L + l0 + j;
        float acc0 = 0.f, acc1 = 0.f;
#pragma unroll 4
        for (int d = 0; d < IND / SCHUNK; d += 2) {
            acc0 += Xp[(size_t)d * L] * qr[d];
            acc1 += Xp[(size_t)(d + 1) * L] * qr[d + 1];
        }
        g_spart[(size_t)c * L + l0 + j] = acc0 + acc1;
    }
}

// Per-segment softmax over its contiguous range (reduce 16 partials inline).
__global__ void k_softmax(int L) {
    int s = blockIdx.x; if (s >= g_S) return;
    int st = g_start[s], len = g_len[s];
    __shared__ float red[8];
    __shared__ float bmax, bsum;
    int tid = threadIdx.x, lane = tid & 31, wp = tid >> 5;
    float mx = -3e38f;
    for (int i = tid; i < len; i += 256) {
        float sc = 0.f;
#pragma unroll
        for (int c = 0; c < SCHUNK; c++) sc += g_spart[(size_t)c * L + st + i];
        g_w[st + i] = sc;
        mx = fmaxf(mx, sc);
    }
    mx = warpMax(mx);
    if (lane == 0) red[wp] = mx;
    __syncthreads();
    if (tid == 0) {
        float m = red[0];
        for (int k = 1; k < 8; k++) m = fmaxf(m, red[k]);
        bmax = m;
    }
    __syncthreads();
    float m = bmax, sum = 0.f;
    for (int i = tid; i < len; i += 256) {
        float e = expf(g_w[st + i] - m);
        g_w[st + i] = e;
        sum += e;
    }
    sum = warpSum(sum);
    if (lane == 0) red[wp] = sum;
    __syncthreads();
    if (tid == 0) {
        float z = 0.f;
        for (int k = 0; k < 8; k++) z += red[k];
        bsum = z;
    }
    __syncthreads();
    float inv = 1.f / bsum;
    for (int i = tid; i < len; i += 256) g_w[st + i] *= inv;
}

// Pass 2 over X: one d-row per warp, unrolled x4 (MLP 8).
__global__ void k_xsum(const float* __restrict__ X, int L) {
    int s = blockIdx.y; if (s >= g_S) return;
    int st = g_start[s], len = g_len[s];
    int warp = threadIdx.x >> 5, lane = threadIdx.x & 31;
    int d = blockIdx.x * 8 + warp;
    const float* Xr = X + (size_t)d * L + st;
    const float* wr = g_w + st;
    float acc = 0.f;
    int i = lane;
    for (; i + 96 < len; i += 128) {
        acc += Xr[i] * wr[i]
             + Xr[i + 32] * wr[i + 32]
             + Xr[i + 64] * wr[i + 64]
             + Xr[i + 96] * wr[i + 96];
    }
    for (; i < len; i += 32) acc += Xr[i] * wr[i];
    acc = warpSum(acc);
    if (lane == 0) g_xsum[s * IND + d] = acc;
}

// seg_feat[s][f] = Wv[f] . xsum[s]; build hl_inp = [seg_feat | label_emb].
__global__ void k_segfeat(const float* __restrict__ Wv, const float* __restrict__ lemb) {
    int s = blockIdx.x; if (s >= g_S) return;
    int warp = threadIdx.x >> 5, lane = threadIdx.x & 31;
#pragma unroll
    for (int r = 0; r < 8; r++) {
        int f = warp * 8 + r;
        const float* Wr = Wv + (size_t)f * IND;
        const float* xr = g_xsum + s * IND;
        float acc = 0.f;
        for (int dd = lane; dd < IND; dd += 32) acc += Wr[dd] * xr[dd];
        acc = warpSum(acc);
        if (lane == 0) {
            g_hl[s * 2 * FD + f] = acc;
            g_hl[s * 2 * FD + FD + f] = lemb[g_pred[s] * FD + f];
        }
    }
}

// Entire conv tower in one kernel: 3 blocks (one per sample), 256 threads.
__global__ void k_tower(const float* __restrict__ w0, const float* __restrict__ b0,
                        const float* __restrict__ bw1, const float* __restrict__ bb1,
                        const float* __restrict__ bw2, const float* __restrict__ bb2) {
    __shared__ float inb[128 * NFR];
    __shared__ float A[FD * NFR];
    __shared__ float B[FD * NFR];
    int i = blockIdx.x;
    int tid = threadIdx.x;
    int t = tid & 31;
    int co0 = tid >> 5;          // 0..7
    for (int idx = tid; idx < 128 * NFR; idx += 256) {
        int ci = idx >> 5, tt = idx & 31;
        inb[ci * NFR + tt] = g_hl[g_samp[i * NFR + tt] * 128 + ci];
    }
    __syncthreads();
    // conv0: 128 -> 64 channels
    for (int co = co0; co < FD; co += 8) {
        const float* wp = w0 + co * 128 * 3;
        float acc = b0[co];
        for (int ci = 0; ci < 128; ci++) {
            float xm = (t > 0) ? inb[ci * NFR + t - 1] : 0.f;
            float x0 = inb[ci * NFR + t];
            float xp = (t < NFR - 1) ? inb[ci * NFR + t + 1] : 0.f;
            acc += wp[ci * 3] * xm + wp[ci * 3 + 1] * x0 + wp[ci * 3 + 2] * xp;
        }
        A[co * NFR + t] = acc;
    }
    __syncthreads();
    int w = NFR;
    for (int lvl = 0; lvl < NBLK; lvl++) {
        if (t < w) {
            for (int co = co0; co < FD; co += 8) {
                const float* wp = bw1 + (size_t)(lvl * FD + co) * FD * 3;
                float acc = bb1[lvl * FD + co];
                for (int ci = 0; ci < FD; ci++) {
                    float xm = (t > 0) ? A[ci * NFR + t - 1] : 0.f;
                    float x0 = A[ci * NFR + t];
                    float xp = (t < w - 1) ? A[ci * NFR + t + 1] : 0.f;
                    acc += wp[ci * 3] * xm + wp[ci * 3 + 1] * x0 + wp[ci * 3 + 2] * xp;
                }
                B[co * NFR + t] = leaky(acc);
            }
        }
        __syncthreads();
        int wo = w >> 1;
        float res[8];
        int nres = 0;
        if (t < wo) {
            for (int co = co0; co < FD; co += 8) {
                const float* wp = bw2 + (size_t)(lvl * FD + co) * FD * 3;
                float bb = bb2[lvl * FD + co];
                float a0 = bb, a1 = bb;
                int t0 = 2 * t, t1 = 2 * t + 1;
                for (int ci = 0; ci < FD; ci++) {
                    float wm = wp[ci * 3], wc = wp[ci * 3 + 1], wq = wp[ci * 3 + 2];
                    float xm0 = (t0 > 0) ? B[ci * NFR + t0 - 1] : 0.f;
                    float x00 = B[ci * NFR + t0];
                    float x01 = B[ci * NFR + t1];
                    float xp1 = (t1 < w - 1) ? B[ci * NFR + t1 + 1] : 0.f;
                    a0 += wm * xm0 + wc * x00 + wq * x01;
                    a1 += wm * x00 + wc * x01 + wq * xp1;
                }
                float y0 = leaky(A[co * NFR + t0] + a0);
                float y1 = leaky(A[co * NFR + t1] + a1);
                res[nres++] = fmaxf(y0, y1);
            }
        }
        __syncthreads();
        if (t < wo) {
            int k = 0;
            for (int co = co0; co < FD; co += 8) A[co * NFR + t] = res[k++];
        }
        __syncthreads();
        w = wo;
    }
    if (tid < FD) g_tow[i * FD + tid] = A[tid * NFR];   // w == 1
}

// Input-side GRU gates: GI[dir][s][g] = b_ih + w_ih . [seg_feat|lab|hl_feat]
__global__ void k_gi(const float* __restrict__ w_ih, const float* __restrict__ b_ih) {
    int s = blockIdx.x; if (s >= g_S) return;
    int dir = blockIdx.y;
    __shared__ float rin[3 * FD];
    int tid = threadIdx.x;
    if (tid < 2 * FD) rin[tid] = g_hl[s * 2 * FD + tid];
    else {
        int c = tid - 2 * FD;
        rin[tid] = (g_tow[c] + g_tow[FD + c] + g_tow[2 * FD + c]) * (1.f / 3.f);
    }
    __syncthreads();
    const float* wr = w_ih + (size_t)(dir * 192 + tid) * 192;
    float acc = b_ih[dir * 192 + tid];
#pragma unroll 8
    for (int j = 0; j < 192; j++) acc += wr[j] * rin[j];
    g_gi[(dir * NACT + s) * 192 + tid] = acc;
}

// Bidirectional GRU (both dirs in one block, lockstep) + output projection.
__global__ void k_gruout(const float* __restrict__ w_hh, const float* __restrict__ b_hh,
                         const float* __restrict__ out_w, const float* __restrict__ out_b,
                         float* __restrict__ dout) {
    int tid = threadIdx.x;                 // 384
    int dir = tid / 192, g = tid % 192;
    int S = g_S;
    __shared__ float h[2][FD];
    __shared__ float gh[2][192];
    float wreg[FD];
#pragma unroll
    for (int j = 0; j < FD; j++) wreg[j] = w_hh[(size_t)(dir * 192 + g) * FD + j];
    float bh = b_hh[dir * 192 + g];
    if (g < FD) h[dir][g] = 0.f;
    __syncthreads();
    for (int t = 0; t < S; t++) {
        int s = (dir == 0) ? t : (S - 1 - t);
        float a0 = 0.f, a1 = 0.f, a2 = 0.f, a3 = 0.f;
#pragma unroll
        for (int j = 0; j < FD; j += 4) {
            a0 += wreg[j] * h[dir][j];
            a1 += wreg[j + 1] * h[dir][j + 1];
            a2 += wreg[j + 2] * h[dir][j + 2];
            a3 += wreg[j + 3] * h[dir][j + 3];
        }
        gh[dir][g] = bh + (a0 + a1) + (a2 + a3);
        __syncthreads();
        if (g < FD) {
            const float* gi = g_gi + (size_t)(dir * NACT + s) * 192;
            float r = sigm(gi[g] + gh[dir][g]);
            float z = sigm(gi[FD + g] + gh[dir][FD + g]);
            float n = tanhf(gi[2 * FD + g] + r * gh[dir][2 * FD + g]);
            float hn = (1.f - z) * n + z * h[dir][g];
            h[dir][g] = hn;
            g_h[s * 2 * FD + dir * FD + g] = hn;
        }
        __syncthreads();
    }
    // output projection: refine_pred[s][a]
    for (int idx = tid; idx < S * NACT; idx += 384) {
        int s = idx / NACT, a = idx % NACT;
        const float* wr = out_w + a * 2 * FD;
        const float* hv = g_h + s * 2 * FD;
        float acc = out_b[a];
#pragma unroll 16
        for (int j = 0; j < 2 * FD; j++) acc += wr[j] * hv[j];
        g_rp[idx] = acc;
        dout[idx] = acc;
    }
}

// rollout[a][l] = refine_pred[seg(l)][a]
__global__ void k_rollout(const int* __restrict__ aidx, float* __restrict__ dout, int L, int S) {
    __shared__ float rp_s[NACT * NACT];
    for (int idx = threadIdx.x; idx < S * NACT; idx += 128) rp_s[idx] = g_rp[idx];
    __syncthreads();
    int l = blockIdx.x * 128 + threadIdx.x;
    if (l >= L) return;
    int s = g_val2seg[aidx[l]];
    float* base = dout + (size_t)S * NACT;
#pragma unroll
    for (int a = 0; a < NACT; a++) base[(size_t)a * L + l] = rp_s[s * NACT + a];
}

// ---------------- launch ----------------
extern "C" void kernel_launch(void* const* d_in, const int* in_sizes, int n_in,
                              void* d_out, int out_size) {
    const int*   aidx = (const int*)d_in[0];
    const float* X    = (const float*)d_in[1];
    const float* Wk   = (const float*)d_in[2];
    const float* Wv   = (const float*)d_in[3];
    const float* qemb = (const float*)d_in[4];
    const float* lemb = (const float*)d_in[5];
    const float* c0w  = (const float*)d_in[6];
    const float* c0b  = (const float*)d_in[7];
    const float* bw1  = (const float*)d_in[8];
    const float* bb1  = (const float*)d_in[9];
    const float* bw2  = (const float*)d_in[10];
    const float* bb2  = (const float*)d_in[11];
    const float* wih  = (const float*)d_in[12];
    const float* whh  = (const float*)d_in[13];
    const float* bih  = (const float*)d_in[14];
    const float* bhh  = (const float*)d_in[15];
    const float* ow   = (const float*)d_in[16];
    const float* ob   = (const float*)d_in[17];
    float* out = (float*)d_out;
    int L = in_sizes[0];
    int S = (out_size - NACT * L) / NACT;

    int nl4 = (L + 3) / 4;
    k_init<<<1, 64>>>(aidx, L);
    k_qk<<<dim3(IND / 256, NACT), 256>>>(Wk, qemb);
    k_score<<<dim3((nl4 + 255) / 256, SCHUNK), 256>>>(X, aidx, L);
    k_softmax<<<NACT, 256>>>(L);
    k_xsum<<<dim3(IND / 8, NACT), 256>>>(X, L);
    k_segfeat<<<NACT, 256>>>(Wv, lemb);
    k_tower<<<NSMP, 256>>>(c0w, c0b, bw1, bb1, bw2, bb2);
    k_gi<<<dim3(NACT, 2), 192>>>(wih, bih);
    k_gruout<<<1, 384>>>(whh, bhh, ow, ob, out);
    k_rollout<<<(L + 127) / 128, 128>>>(aidx, out, L, S);
}

// round 10
// speedup vs baseline: 1.8272x; 1.8272x over previous
#include <cuda_runtime.h>
#include <cuda_bf16.h>
#include <stdint.h>
#include <math.h>

#define MAXL   20000
#define NACT   48
#define FD     64
#define IND    2048
#define NFR    32
#define NSMP   3
#define NBLK   5
#define SCHUNK 16

// ---------------- scratch (device globals; no allocation) ----------------
__device__ float g_spart[SCHUNK * MAXL];    // partial scores per d-chunk
__device__ float g_w[MAXL];                 // softmax weights
__device__ int   g_S;
__device__ int   g_start[NACT], g_len[NACT], g_pred[NACT], g_val2seg[NACT];
__device__ int   g_samp[NSMP * NFR];
__device__ float g_qk[NACT * IND];          // (Wk^T q_pred[s]) / 8
__device__ float g_xsum[NACT * IND];        // sum_l w_l x_l per segment
__device__ float g_hl[NACT * 2 * FD];       // [seg_feat | label_emb]
__device__ float g_tow[NSMP * FD];          // conv tower output per sample
__device__ float g_gi[2 * NACT * 3 * FD];   // input-side GRU gates
__device__ float g_h[NACT * 2 * FD];        // [h_fwd | h_bwd]
__device__ float g_rp[NACT * NACT];         // refine_pred

// ---------------- helpers ----------------
__device__ __forceinline__ float warpSum(float v) {
#pragma unroll
    for (int o = 16; o; o >>= 1) v += __shfl_xor_sync(0xffffffffu, v, o);
    return v;
}
__device__ __forceinline__ float warpMax(float v) {
#pragma unroll
    for (int o = 16; o; o >>= 1) v = fmaxf(v, __shfl_xor_sync(0xffffffffu, v, o));
    return v;
}
__device__ __forceinline__ float leaky(float x) { return x >= 0.f ? x : 0.1f * x; }
__device__ __forceinline__ float sigm(float x)  { return 1.f / (1.f + expf(-x)); }
__device__ __forceinline__ uint32_t rotl32(uint32_t x, int r) { return (x << r) | (x >> (32 - r)); }

// Threefry-2x32-20 (jax-exact)
__device__ uint2 tf2x32(uint32_t k0, uint32_t k1, uint32_t x0, uint32_t x1) {
    uint32_t ks2 = k0 ^ k1 ^ 0x1BD11BDAu;
    x0 += k0; x1 += k1;
    x0 += x1; x1 = rotl32(x1, 13); x1 ^= x0;
    x0 += x1; x1 = rotl32(x1, 15); x1 ^= x0;
    x0 += x1; x1 = rotl32(x1, 26); x1 ^= x0;
    x0 += x1; x1 = rotl32(x1, 6);  x1 ^= x0;
    x0 += k1; x1 += ks2 + 1u;
    x0 += x1; x1 = rotl32(x1, 17); x1 ^= x0;
    x0 += x1; x1 = rotl32(x1, 29); x1 ^= x0;
    x0 += x1; x1 = rotl32(x1, 16); x1 ^= x0;
    x0 += x1; x1 = rotl32(x1, 24); x1 ^= x0;
    x0 += ks2; x1 += k0 + 2u;
    x0 += x1; x1 = rotl32(x1, 13); x1 ^= x0;
    x0 += x1; x1 = rotl32(x1, 15); x1 ^= x0;
    x0 += x1; x1 = rotl32(x1, 26); x1 ^= x0;
    x0 += x1; x1 = rotl32(x1, 6);  x1 ^= x0;
    x0 += k0; x1 += k1 + 3u;
    x0 += x1; x1 = rotl32(x1, 17); x1 ^= x0;
    x0 += x1; x1 = rotl32(x1, 29); x1 ^= x0;
    x0 += x1; x1 = rotl32(x1, 16); x1 ^= x0;
    x0 += x1; x1 = rotl32(x1, 24); x1 ^= x0;
    x0 += k1; x1 += ks2 + 4u;
    x0 += x1; x1 = rotl32(x1, 13); x1 ^= x0;
    x0 += x1; x1 = rotl32(x1, 15); x1 ^= x0;
    x0 += x1; x1 = rotl32(x1, 26); x1 ^= x0;
    x0 += x1; x1 = rotl32(x1, 6);  x1 ^= x0;
    x0 += ks2; x1 += k0 + 5u;
    return make_uint2(x0, x1);
}

// ---------------- kernels ----------------

// Segments (sorted action_idx) + jax-PRNG sample indices, one tiny block.
__global__ void k_init(const int* __restrict__ a, int L) {
    __shared__ int lo_s[NACT + 1];
    __shared__ int S_s;
    __shared__ uint32_t bits[NACT];
    __shared__ int sel[NACT];
    __shared__ uint32_t sk0, sk1;
    int tid = threadIdx.x;
    if (tid <= NACT) {
        int lo = 0, hi = L;
        while (lo < hi) { int mid = (lo + hi) >> 1; if (a[mid] < tid) lo = mid + 1; else hi = mid; }
        lo_s[tid] = lo;
    }
    __syncthreads();
    if (tid == 0) {
        int s = 0;
        for (int vv = 0; vv < NACT; vv++) {
            int st = lo_s[vv], en = lo_s[vv + 1];
            if (en > st) { g_val2seg[vv] = s; g_start[s] = st; g_len[s] = en - st; g_pred[s] = vv; s++; }
            else g_val2seg[vv] = 0;
        }
        g_S = s; S_s = s;
    }
    __syncthreads();
    int S = S_s;
    for (int i = 0; i < NSMP; i++) {
        if (tid == 0) {
            uint2 fk  = tf2x32(0u, 42u, 0u, (uint32_t)i);   // fold_in(key(42), i)
            uint2 sub = tf2x32(fk.x, fk.y, 0u, 1u);          // split -> subkey
            sk0 = sub.x; sk1 = sub.y;
        }
        __syncthreads();
        if (tid < S) {
            uint2 o = tf2x32(sk0, sk1, 0u, (uint32_t)tid);   // partitionable random_bits
            bits[tid] = o.x ^ o.y;
        }
        __syncthreads();
        if (tid < S) {
            uint32_t kj = bits[tid];
            int rank = 0;
            for (int m = 0; m < S; m++) {
                uint32_t km = bits[m];
                rank += ((km < kj) || (km == kj && m < tid)) ? 1 : 0;
            }
            sel[tid] = (rank < NFR) ? 1 : 0;
        }
        __syncthreads();
        if (tid == 0) {
            int c = 0;
            for (int j = 0; j < S && c < NFR; j++)
                if (sel[j]) g_samp[i * NFR + c++] = j;
            while (c < NFR) { g_samp[i * NFR + c] = c % (S > 0 ? S : 1); c++; }
        }
        __syncthreads();
    }
}

// qk[s][d] = (1/8) * sum_f Wk[f][d] * query_emb[pred[s]][f]
__global__ void k_qk(const float* __restrict__ Wk, const float* __restrict__ qemb) {
    int s = blockIdx.y; if (s >= g_S) return;
    int d = blockIdx.x * 256 + threadIdx.x;
    const float* q = qemb + g_pred[s] * FD;
    float acc = 0.f;
#pragma unroll
    for (int f = 0; f < FD; f++) acc += Wk[(size_t)f * IND + d] * q[f];
    g_qk[s * IND + d] = acc * 0.125f;
}

// Pass 1 over X (round-3-proven shape): thread per l, 16 d-chunks of 128,
// 8 independent accumulators (8 scalar loads in flight).
__global__ void k_score(const float* __restrict__ X, const int* __restrict__ a, int L) {
    int l = blockIdx.x * 256 + threadIdx.x;
    if (l >= L) return;
    int s = g_val2seg[a[l]];
    int dbase = blockIdx.y * (IND / SCHUNK);   // 128 d's per chunk
    const float* qr = g_qk + s * IND + dbase;
    const float* Xp = X + (size_t)dbase * L + l;
    float a0 = 0.f, a1 = 0.f, a2 = 0.f, a3 = 0.f;
    float a4 = 0.f, a5 = 0.f, a6 = 0.f, a7 = 0.f;
    for (int d = 0; d < IND / SCHUNK; d += 8) {
        a0 += Xp[(size_t)d * L]       * qr[d];
        a1 += Xp[(size_t)(d + 1) * L] * qr[d + 1];
        a2 += Xp[(size_t)(d + 2) * L] * qr[d + 2];
        a3 += Xp[(size_t)(d + 3) * L] * qr[d + 3];
        a4 += Xp[(size_t)(d + 4) * L] * qr[d + 4];
        a5 += Xp[(size_t)(d + 5) * L] * qr[d + 5];
        a6 += Xp[(size_t)(d + 6) * L] * qr[d + 6];
        a7 += Xp[(size_t)(d + 7) * L] * qr[d + 7];
    }
    g_spart[(size_t)blockIdx.y * L + l] = ((a0 + a1) + (a2 + a3)) + ((a4 + a5) + (a6 + a7));
}

// Per-segment softmax over its contiguous range (reduce 16 partials inline).
__global__ void k_softmax(int L) {
    int s = blockIdx.x; if (s >= g_S) return;
    int st = g_start[s], len = g_len[s];
    __shared__ float red[8];
    __shared__ float bmax, bsum;
    int tid = threadIdx.x, lane = tid & 31, wp = tid >> 5;
    float mx = -3e38f;
    for (int i = tid; i < len; i += 256) {
        float sc = 0.f;
#pragma unroll
        for (int c = 0; c < SCHUNK; c++) sc += g_spart[(size_t)c * L + st + i];
        g_w[st + i] = sc;
        mx = fmaxf(mx, sc);
    }
    mx = warpMax(mx);
    if (lane == 0) red[wp] = mx;
    __syncthreads();
    if (tid == 0) {
        float m = red[0];
        for (int k = 1; k < 8; k++) m = fmaxf(m, red[k]);
        bmax = m;
    }
    __syncthreads();
    float m = bmax, sum = 0.f;
    for (int i = tid; i < len; i += 256) {
        float e = expf(g_w[st + i] - m);
        g_w[st + i] = e;
        sum += e;
    }
    sum = warpSum(sum);
    if (lane == 0) red[wp] = sum;
    __syncthreads();
    if (tid == 0) {
        float z = 0.f;
        for (int k = 0; k < 8; k++) z += red[k];
        bsum = z;
    }
    __syncthreads();
    float inv = 1.f / bsum;
    for (int i = tid; i < len; i += 256) g_w[st + i] *= inv;
}

// Pass 2 over X (round-3-proven shape): 4 d-rows per warp, 2-acc unroll.
__global__ void k_xsum(const float* __restrict__ X, int L) {
    int s = blockIdx.y; if (s >= g_S) return;
    int st = g_start[s], len = g_len[s];
    int warp = threadIdx.x >> 5, lane = threadIdx.x & 31;
#pragma unroll
    for (int r = 0; r < 4; r++) {
        int d = blockIdx.x * 32 + warp * 4 + r;
        const float* Xr = X + (size_t)d * L + st;
        const float* wr = g_w + st;
        float acc0 = 0.f, acc1 = 0.f;
        int i = lane;
        for (; i + 32 < len; i += 64) {
            acc0 += Xr[i] * wr[i];
            acc1 += Xr[i + 32] * wr[i + 32];
        }
        if (i < len) acc0 += Xr[i] * wr[i];
        float acc = warpSum(acc0 + acc1);
        if (lane == 0) g_xsum[s * IND + d] = acc;
    }
}

// seg_feat[s][f] = Wv[f] . xsum[s]; build hl_inp = [seg_feat | label_emb].
__global__ void k_segfeat(const float* __restrict__ Wv, const float* __restrict__ lemb) {
    int s = blockIdx.x; if (s >= g_S) return;
    int warp = threadIdx.x >> 5, lane = threadIdx.x & 31;
#pragma unroll
    for (int r = 0; r < 8; r++) {
        int f = warp * 8 + r;
        const float* Wr = Wv + (size_t)f * IND;
        const float* xr = g_xsum + s * IND;
        float acc = 0.f;
        for (int dd = lane; dd < IND; dd += 32) acc += Wr[dd] * xr[dd];
        acc = warpSum(acc);
        if (lane == 0) {
            g_hl[s * 2 * FD + f] = acc;
            g_hl[s * 2 * FD + FD + f] = lemb[g_pred[s] * FD + f];
        }
    }
}

// Entire conv tower in one kernel: 3 blocks (one per sample), 1024 threads
// (32 co-warps x 32 t) -> only 2 co iterations per thread at conv0.
__global__ void k_tower(const float* __restrict__ w0, const float* __restrict__ b0,
                        const float* __restrict__ bw1, const float* __restrict__ bb1,
                        const float* __restrict__ bw2, const float* __restrict__ bb2) {
    __shared__ float inb[128 * NFR];
    __shared__ float A[FD * NFR];
    __shared__ float B[FD * NFR];
    int i = blockIdx.x;
    int tid = threadIdx.x;
    int t = tid & 31;
    int co0 = tid >> 5;          // 0..31
    for (int idx = tid; idx < 128 * NFR; idx += 1024) {
        int ci = idx >> 5, tt = idx & 31;
        inb[ci * NFR + tt] = g_hl[g_samp[i * NFR + tt] * 128 + ci];
    }
    __syncthreads();
    // conv0: 128 -> 64 channels (each thread: 2 output channels)
#pragma unroll
    for (int cq = 0; cq < 2; cq++) {
        int co = co0 + cq * 32;
        const float* wp = w0 + co * 128 * 3;
        float acc = b0[co];
        for (int ci = 0; ci < 128; ci++) {
            float xm = (t > 0) ? inb[ci * NFR + t - 1] : 0.f;
            float x0 = inb[ci * NFR + t];
            float xp = (t < NFR - 1) ? inb[ci * NFR + t + 1] : 0.f;
            acc += wp[ci * 3] * xm + wp[ci * 3 + 1] * x0 + wp[ci * 3 + 2] * xp;
        }
        A[co * NFR + t] = acc;
    }
    __syncthreads();
    int w = NFR;
    for (int lvl = 0; lvl < NBLK; lvl++) {
        if (t < w) {
#pragma unroll
            for (int cq = 0; cq < 2; cq++) {
                int co = co0 + cq * 32;
                const float* wp = bw1 + (size_t)(lvl * FD + co) * FD * 3;
                float acc = bb1[lvl * FD + co];
                for (int ci = 0; ci < FD; ci++) {
                    float xm = (t > 0) ? A[ci * NFR + t - 1] : 0.f;
                    float x0 = A[ci * NFR + t];
                    float xp = (t < w - 1) ? A[ci * NFR + t + 1] : 0.f;
                    acc += wp[ci * 3] * xm + wp[ci * 3 + 1] * x0 + wp[ci * 3 + 2] * xp;
                }
                B[co * NFR + t] = leaky(acc);
            }
        }
        __syncthreads();
        int wo = w >> 1;
        float res[2];
        if (t < wo) {
#pragma unroll
            for (int cq = 0; cq < 2; cq++) {
                int co = co0 + cq * 32;
                const float* wp = bw2 + (size_t)(lvl * FD + co) * FD * 3;
                float bb = bb2[lvl * FD + co];
                float a0 = bb, a1 = bb;
                int t0 = 2 * t, t1 = 2 * t + 1;
                for (int ci = 0; ci < FD; ci++) {
                    float wm = wp[ci * 3], wc = wp[ci * 3 + 1], wq = wp[ci * 3 + 2];
                    float xm0 = (t0 > 0) ? B[ci * NFR + t0 - 1] : 0.f;
                    float x00 = B[ci * NFR + t0];
                    float x01 = B[ci * NFR + t1];
                    float xp1 = (t1 < w - 1) ? B[ci * NFR + t1 + 1] : 0.f;
                    a0 += wm * xm0 + wc * x00 + wq * x01;
                    a1 += wm * x00 + wc * x01 + wq * xp1;
                }
                float y0 = leaky(A[co * NFR + t0] + a0);
                float y1 = leaky(A[co * NFR + t1] + a1);
                res[cq] = fmaxf(y0, y1);
            }
        }
        __syncthreads();
        if (t < wo) {
#pragma unroll
            for (int cq = 0; cq < 2; cq++) A[(co0 + cq * 32) * NFR + t] = res[cq];
        }
        __syncthreads();
        w = wo;
    }
    if (tid < FD) g_tow[i * FD + tid] = A[tid * NFR];   // w == 1
}

// Input-side GRU gates: GI[dir][s][g] = b_ih + w_ih . [seg_feat|lab|hl_feat]
__global__ void k_gi(const float* __restrict__ w_ih, const float* __restrict__ b_ih) {
    int s = blockIdx.x; if (s >= g_S) return;
    int dir = blockIdx.y;
    __shared__ float rin[3 * FD];
    int tid = threadIdx.x;
    if (tid < 2 * FD) rin[tid] = g_hl[s * 2 * FD + tid];
    else {
        int c = tid - 2 * FD;
        rin[tid] = (g_tow[c] + g_tow[FD + c] + g_tow[2 * FD + c]) * (1.f / 3.f);
    }
    __syncthreads();
    const float* wr = w_ih + (size_t)(dir * 192 + tid) * 192;
    float acc = b_ih[dir * 192 + tid];
#pragma unroll 8
    for (int j = 0; j < 192; j++) acc += wr[j] * rin[j];
    g_gi[(dir * NACT + s) * 192 + tid] = acc;
}

// Bidirectional GRU (both dirs in one block, lockstep) + output projection.
__global__ void k_gruout(const float* __restrict__ w_hh, const float* __restrict__ b_hh,
                         const float* __restrict__ out_w, const float* __restrict__ out_b,
                         float* __restrict__ dout) {
    int tid = threadIdx.x;                 // 384
    int dir = tid / 192, g = tid % 192;
    int S = g_S;
    __shared__ float h[2][FD];
    __shared__ float gh[2][192];
    float wreg[FD];
#pragma unroll
    for (int j = 0; j < FD; j++) wreg[j] = w_hh[(size_t)(dir * 192 + g) * FD + j];
    float bh = b_hh[dir * 192 + g];
    if (g < FD) h[dir][g] = 0.f;
    __syncthreads();
    for (int t = 0; t < S; t++) {
        int s = (dir == 0) ? t : (S - 1 - t);
        float a0 = 0.f, a1 = 0.f, a2 = 0.f, a3 = 0.f;
#pragma unroll
        for (int j = 0; j < FD; j += 4) {
            a0 += wreg[j] * h[dir][j];
            a1 += wreg[j + 1] * h[dir][j + 1];
            a2 += wreg[j + 2] * h[dir][j + 2];
            a3 += wreg[j + 3] * h[dir][j + 3];
        }
        gh[dir][g] = bh + (a0 + a1) + (a2 + a3);
        __syncthreads();
        if (g < FD) {
            const float* gi = g_gi + (size_t)(dir * NACT + s) * 192;
            float r = sigm(gi[g] + gh[dir][g]);
            float z = sigm(gi[FD + g] + gh[dir][FD + g]);
            float n = tanhf(gi[2 * FD + g] + r * gh[dir][2 * FD + g]);
            float hn = (1.f - z) * n + z * h[dir][g];
            h[dir][g] = hn;
            g_h[s * 2 * FD + dir * FD + g] = hn;
        }
        __syncthreads();
    }
    // output projection: refine_pred[s][a]
    for (int idx = tid; idx < S * NACT; idx += 384) {
        int s = idx / NACT, a = idx % NACT;
        const float* wr = out_w + a * 2 * FD;
        const float* hv = g_h + s * 2 * FD;
        float acc = out_b[a];
#pragma unroll 16
        for (int j = 0; j < 2 * FD; j++) acc += wr[j] * hv[j];
        g_rp[idx] = acc;
        dout[idx] = acc;
    }
}

// rollout[a][l] = refine_pred[seg(l)][a]
__global__ void k_rollout(const int* __restrict__ aidx, float* __restrict__ dout, int L, int S) {
    __shared__ float rp_s[NACT * NACT];
    for (int idx = threadIdx.x; idx < S * NACT; idx += 128) rp_s[idx] = g_rp[idx];
    __syncthreads();
    int l = blockIdx.x * 128 + threadIdx.x;
    if (l >= L) return;
    int s = g_val2seg[aidx[l]];
    float* base = dout + (size_t)S * NACT;
#pragma unroll
    for (int a = 0; a < NACT; a++) base[(size_t)a * L + l] = rp_s[s * NACT + a];
}

// ---------------- launch ----------------
extern "C" void kernel_launch(void* const* d_in, const int* in_sizes, int n_in,
                              void* d_out, int out_size) {
    const int*   aidx = (const int*)d_in[0];
    const float* X    = (const float*)d_in[1];
    const float* Wk   = (const float*)d_in[2];
    const float* Wv   = (const float*)d_in[3];
    const float* qemb = (const float*)d_in[4];
    const float* lemb = (const float*)d_in[5];
    const float* c0w  = (const float*)d_in[6];
    const float* c0b  = (const float*)d_in[7];
    const float* bw1  = (const float*)d_in[8];
    const float* bb1  = (const float*)d_in[9];
    const float* bw2  = (const float*)d_in[10];
    const float* bb2  = (const float*)d_in[11];
    const float* wih  = (const float*)d_in[12];
    const float* whh  = (const float*)d_in[13];
    const float* bih  = (const float*)d_in[14];
    const float* bhh  = (const float*)d_in[15];
    const float* ow   = (const float*)d_in[16];
    const float* ob   = (const float*)d_in[17];
    float* out = (float*)d_out;
    int L = in_sizes[0];
    int S = (out_size - NACT * L) / NACT;

    k_init<<<1, 64>>>(aidx, L);
    k_qk<<<dim3(IND / 256, NACT), 256>>>(Wk, qemb);
    k_score<<<dim3((L + 255) / 256, SCHUNK), 256>>>(X, aidx, L);
    k_softmax<<<NACT, 256>>>(L);
    k_xsum<<<dim3(IND / 32, NACT), 256>>>(X, L);
    k_segfeat<<<NACT, 256>>>(Wv, lemb);
    k_tower<<<NSMP, 1024>>>(c0w, c0b, bw1, bb1, bw2, bb2);
    k_gi<<<dim3(NACT, 2), 192>>>(wih, bih);
    k_gruout<<<1, 384>>>(whh, bhh, ow, ob, out);
    k_rollout<<<(L + 127) / 128, 128>>>(aidx, out, L, S);
}

// round 13
// speedup vs baseline: 3.1658x; 1.7326x over previous
#include <cuda_runtime.h>
#include <cuda_bf16.h>
#include <stdint.h>
#include <math.h>

#define MAXL   20000
#define NACT   48
#define FD     64
#define IND    2048
#define NFR    32
#define NSMP   3
#define NBLK   5
#define SCHUNK 8

// ---------------- scratch (device globals; no allocation) ----------------
__device__ float g_spart[SCHUNK * MAXL];    // partial scores per d-chunk
__device__ float g_w[MAXL];                 // softmax weights
__device__ int   g_S;
__device__ int   g_start[NACT], g_len[NACT], g_pred[NACT], g_val2seg[NACT];
__device__ int   g_samp[NSMP * NFR];
__device__ float g_qk[NACT * IND];          // (Wk^T q_pred[s]) / 8
__device__ float g_xsum[NACT * IND];        // sum_l w_l x_l per segment
__device__ float g_hl[NACT * 2 * FD];       // [seg_feat | label_emb]
__device__ float g_cbufA[NSMP * FD * NFR];  // conv ping
__device__ float g_cbufB[NSMP * FD * NFR];  // conv pong
__device__ float g_gi[2 * NACT * 3 * FD];   // input-side GRU gates
__device__ float g_h[NACT * 2 * FD];        // [h_fwd | h_bwd]
__device__ float g_rp[NACT * NACT];         // refine_pred

// ---------------- helpers ----------------
__device__ __forceinline__ float warpSum(float v) {
#pragma unroll
    for (int o = 16; o; o >>= 1) v += __shfl_xor_sync(0xffffffffu, v, o);
    return v;
}
__device__ __forceinline__ float warpMax(float v) {
#pragma unroll
    for (int o = 16; o; o >>= 1) v = fmaxf(v, __shfl_xor_sync(0xffffffffu, v, o));
    return v;
}
__device__ __forceinline__ float leaky(float x) { return x >= 0.f ? x : 0.1f * x; }
__device__ __forceinline__ float sigm(float x)  { return 1.f / (1.f + expf(-x)); }
__device__ __forceinline__ uint32_t rotl32(uint32_t x, int r) { return (x << r) | (x >> (32 - r)); }

// Threefry-2x32-20 (jax-exact)
__device__ uint2 tf2x32(uint32_t k0, uint32_t k1, uint32_t x0, uint32_t x1) {
    uint32_t ks2 = k0 ^ k1 ^ 0x1BD11BDAu;
    x0 += k0; x1 += k1;
    x0 += x1; x1 = rotl32(x1, 13); x1 ^= x0;
    x0 += x1; x1 = rotl32(x1, 15); x1 ^= x0;
    x0 += x1; x1 = rotl32(x1, 26); x1 ^= x0;
    x0 += x1; x1 = rotl32(x1, 6);  x1 ^= x0;
    x0 += k1; x1 += ks2 + 1u;
    x0 += x1; x1 = rotl32(x1, 17); x1 ^= x0;
    x0 += x1; x1 = rotl32(x1, 29); x1 ^= x0;
    x0 += x1; x1 = rotl32(x1, 16); x1 ^= x0;
    x0 += x1; x1 = rotl32(x1, 24); x1 ^= x0;
    x0 += ks2; x1 += k0 + 2u;
    x0 += x1; x1 = rotl32(x1, 13); x1 ^= x0;
    x0 += x1; x1 = rotl32(x1, 15); x1 ^= x0;
    x0 += x1; x1 = rotl32(x1, 26); x1 ^= x0;
    x0 += x1; x1 = rotl32(x1, 6);  x1 ^= x0;
    x0 += k0; x1 += k1 + 3u;
    x0 += x1; x1 = rotl32(x1, 17); x1 ^= x0;
    x0 += x1; x1 = rotl32(x1, 29); x1 ^= x0;
    x0 += x1; x1 = rotl32(x1, 16); x1 ^= x0;
    x0 += x1; x1 = rotl32(x1, 24); x1 ^= x0;
    x0 += k1; x1 += ks2 + 4u;
    x0 += x1; x1 = rotl32(x1, 13); x1 ^= x0;
    x0 += x1; x1 = rotl32(x1, 15); x1 ^= x0;
    x0 += x1; x1 = rotl32(x1, 26); x1 ^= x0;
    x0 += x1; x1 = rotl32(x1, 6);  x1 ^= x0;
    x0 += ks2; x1 += k0 + 5u;
    return make_uint2(x0, x1);
}

// ---------------- kernels ----------------

// Segments (sorted action_idx) + jax-PRNG sample indices, one tiny block.
__global__ void k_init(const int* __restrict__ a, int L) {
    __shared__ int lo_s[NACT + 1];
    __shared__ int S_s;
    __shared__ uint32_t bits[NACT];
    __shared__ int sel[NACT];
    __shared__ uint32_t sk0, sk1;
    int tid = threadIdx.x;
    if (tid <= NACT) {
        int lo = 0, hi = L;
        while (lo < hi) { int mid = (lo + hi) >> 1; if (a[mid] < tid) lo = mid + 1; else hi = mid; }
        lo_s[tid] = lo;
    }
    __syncthreads();
    if (tid == 0) {
        int s = 0;
        for (int vv = 0; vv < NACT; vv++) {
            int st = lo_s[vv], en = lo_s[vv + 1];
            if (en > st) { g_val2seg[vv] = s; g_start[s] = st; g_len[s] = en - st; g_pred[s] = vv; s++; }
            else g_val2seg[vv] = 0;
        }
        g_S = s; S_s = s;
    }
    __syncthreads();
    int S = S_s;
    for (int i = 0; i < NSMP; i++) {
        if (tid == 0) {
            uint2 fk  = tf2x32(0u, 42u, 0u, (uint32_t)i);   // fold_in(key(42), i)
            uint2 sub = tf2x32(fk.x, fk.y, 0u, 1u);          // split -> subkey
            sk0 = sub.x; sk1 = sub.y;
        }
        __syncthreads();
        if (tid < S) {
            uint2 o = tf2x32(sk0, sk1, 0u, (uint32_t)tid);   // partitionable random_bits
            bits[tid] = o.x ^ o.y;
        }
        __syncthreads();
        if (tid < S) {
            uint32_t kj = bits[tid];
            int rank = 0;
            for (int m = 0; m < S; m++) {
                uint32_t km = bits[m];
                rank += ((km < kj) || (km == kj && m < tid)) ? 1 : 0;
            }
            sel[tid] = (rank < NFR) ? 1 : 0;
        }
        __syncthreads();
        if (tid == 0) {
            int c = 0;
            for (int j = 0; j < S && c < NFR; j++)
                if (sel[j]) g_samp[i * NFR + c++] = j;
            while (c < NFR) { g_samp[i * NFR + c] = c % (S > 0 ? S : 1); c++; }
        }
        __syncthreads();
    }
}

// qk[s][d] = (1/8) * sum_f Wk[f][d] * query_emb[pred[s]][f]
__global__ void k_qk(const float* __restrict__ Wk, const float* __restrict__ qemb) {
    int s = blockIdx.y; if (s >= g_S) return;
    int d = blockIdx.x * 256 + threadIdx.x;
    const float* q = qemb + g_pred[s] * FD;
    float acc = 0.f;
#pragma unroll
    for (int f = 0; f < FD; f++) acc += Wk[(size_t)f * IND + d] * q[f];
    g_qk[s * IND + d] = acc * 0.125f;
}

// Pass 1 over X: partial scores per d-chunk (round-3-proven shape).
__global__ void k_score(const float* __restrict__ X, const int* __restrict__ a, int L) {
    int l = blockIdx.x * 256 + threadIdx.x;
    if (l >= L) return;
    int s = g_val2seg[a[l]];
    int dbase = blockIdx.y * (IND / SCHUNK);
    const float* qr = g_qk + s * IND + dbase;
    const float* Xp = X + (size_t)dbase * L + l;
    float a0 = 0.f, a1 = 0.f, a2 = 0.f, a3 = 0.f;
    for (int d = 0; d < IND / SCHUNK; d += 4) {
        a0 += Xp[(size_t)d * L]       * qr[d];
        a1 += Xp[(size_t)(d + 1) * L] * qr[d + 1];
        a2 += Xp[(size_t)(d + 2) * L] * qr[d + 2];
        a3 += Xp[(size_t)(d + 3) * L] * qr[d + 3];
    }
    g_spart[blockIdx.y * L + l] = (a0 + a1) + (a2 + a3);
}

// Per-segment softmax over its contiguous range.
__global__ void k_softmax(int L) {
    int s = blockIdx.x; if (s >= g_S) return;
    int st = g_start[s], len = g_len[s];
    __shared__ float red[8];
    __shared__ float bmax, bsum;
    int tid = threadIdx.x, lane = tid & 31, wp = tid >> 5;
    float mx = -3e38f;
    for (int i = tid; i < len; i += 256) {
        float sc = 0.f;
#pragma unroll
        for (int c = 0; c < SCHUNK; c++) sc += g_spart[c * L + st + i];
        g_w[st + i] = sc;
        mx = fmaxf(mx, sc);
    }
    mx = warpMax(mx);
    if (lane == 0) red[wp] = mx;
    __syncthreads();
    if (tid == 0) {
        float m = red[0];
        for (int k = 1; k < 8; k++) m = fmaxf(m, red[k]);
        bmax = m;
    }
    __syncthreads();
    float m = bmax, sum = 0.f;
    for (int i = tid; i < len; i += 256) {
        float e = expf(g_w[st + i] - m);
        g_w[st + i] = e;
        sum += e;
    }
    sum = warpSum(sum);
    if (lane == 0) red[wp] = sum;
    __syncthreads();
    if (tid == 0) {
        float z = 0.f;
        for (int k = 0; k < 8; k++) z += red[k];
        bsum = z;
    }
    __syncthreads();
    float inv = 1.f / bsum;
    for (int i = tid; i < len; i += 256) g_w[st + i] *= inv;
}

// Pass 2 over X: xsum[s][d] (round-3-proven shape: 4 d-rows per warp).
__global__ void k_xsum(const float* __restrict__ X, int L) {
    int s = blockIdx.y; if (s >= g_S) return;
    int st = g_start[s], len = g_len[s];
    int warp = threadIdx.x >> 5, lane = threadIdx.x & 31;
#pragma unroll
    for (int r = 0; r < 4; r++) {
        int d = blockIdx.x * 32 + warp * 4 + r;
        const float* Xr = X + (size_t)d * L + st;
        const float* wr = g_w + st;
        float acc = 0.f;
        for (int i = lane; i < len; i += 32) acc += Xr[i] * wr[i];
        acc = warpSum(acc);
        if (lane == 0) g_xsum[s * IND + d] = acc;
    }
}

// seg_feat[s][f] = Wv[f] . xsum[s]; build hl_inp = [seg_feat | label_emb].
__global__ void k_segfeat(const float* __restrict__ Wv, const float* __restrict__ lemb) {
    int s = blockIdx.x; if (s >= g_S) return;
    int warp = threadIdx.x >> 5, lane = threadIdx.x & 31;
#pragma unroll
    for (int r = 0; r < 8; r++) {
        int f = warp * 8 + r;
        const float* Wr = Wv + (size_t)f * IND;
        const float* xr = g_xsum + s * IND;
        float acc = 0.f;
        for (int dd = lane; dd < IND; dd += 32) acc += Wr[dd] * xr[dd];
        acc = warpSum(acc);
        if (lane == 0) {
            g_hl[s * 2 * FD + f] = acc;
            g_hl[s * 2 * FD + FD + f] = lemb[g_pred[s] * FD + f];
        }
    }
}

// conv0: gathered samples [128ch,32t] -> 64ch, k=3 SAME.
__global__ void k_conv0(const float* __restrict__ w0, const float* __restrict__ b0) {
    __shared__ float in_s[128 * NFR];
    int i = blockIdx.y, co = blockIdx.x, t = threadIdx.x;
    for (int idx = t; idx < 128 * NFR; idx += 32) {
        int ci = idx >> 5, tt = idx & 31;
        in_s[ci * NFR + tt] = g_hl[g_samp[i * NFR + tt] * 128 + ci];
    }
    __syncthreads();
    float acc = b0[co];
    for (int ci = 0; ci < 128; ci++) {
        const float* wp = w0 + (co * 128 + ci) * 3;
        float xm = (t > 0) ? in_s[ci * NFR + t - 1] : 0.f;
        float x0 = in_s[ci * NFR + t];
        float xp = (t < NFR - 1) ? in_s[ci * NFR + t + 1] : 0.f;
        acc += wp[0] * xm + wp[1] * x0 + wp[2] * xp;
    }
    g_cbufA[(i * FD + co) * NFR + t] = acc;
}

// level conv #1: leaky(conv(in)) -> cbufB
__global__ void k_convA(const float* __restrict__ w1, const float* __restrict__ b1, int lvl, int w) {
    __shared__ float in_s[FD * NFR];
    int i = blockIdx.y, co = blockIdx.x, t = threadIdx.x;
    for (int idx = t; idx < FD * w; idx += 32) {
        int ci = idx / w, tt = idx - ci * w;
        in_s[ci * NFR + tt] = g_cbufA[(i * FD + ci) * NFR + tt];
    }
    __syncthreads();
    if (t < w) {
        const float* wp = w1 + (size_t)(lvl * FD + co) * FD * 3;
        float acc = b1[lvl * FD + co];
        for (int ci = 0; ci < FD; ci++) {
            float xm = (t > 0) ? in_s[ci * NFR + t - 1] : 0.f;
            float x0 = in_s[ci * NFR + t];
            float xp = (t < w - 1) ? in_s[ci * NFR + t + 1] : 0.f;
            acc += wp[ci * 3] * xm + wp[ci * 3 + 1] * x0 + wp[ci * 3 + 2] * xp;
        }
        g_cbufB[(i * FD + co) * NFR + t] = leaky(acc);
    }
}

// level conv #2 + residual + leaky + maxpool/2 -> cbufA
__global__ void k_convB(const float* __restrict__ w2, const float* __restrict__ b2, int lvl, int w) {
    __shared__ float tm[FD * NFR];
    int i = blockIdx.y, co = blockIdx.x, t = threadIdx.x;
    for (int idx = t; idx < FD * w; idx += 32) {
        int ci = idx / w, tt = idx - ci * w;
        tm[ci * NFR + tt] = g_cbufB[(i * FD + ci) * NFR + tt];
    }
    int wo = w >> 1;
    float r0 = 0.f, r1 = 0.f;
    if (t < wo) {
        r0 = g_cbufA[(i * FD + co) * NFR + 2 * t];
        r1 = g_cbufA[(i * FD + co) * NFR + 2 * t + 1];
    }
    __syncthreads();
    if (t < wo) {
        const float* wp = w2 + (size_t)(lvl * FD + co) * FD * 3;
        float b = b2[lvl * FD + co];
        float a0 = b, a1 = b;
        int t0 = 2 * t, t1 = 2 * t + 1;
        for (int ci = 0; ci < FD; ci++) {
            float wm = wp[ci * 3], wc = wp[ci * 3 + 1], wq = wp[ci * 3 + 2];
            float xm0 = (t0 > 0) ? tm[ci * NFR + t0 - 1] : 0.f;
            float x00 = tm[ci * NFR + t0];
            float x01 = tm[ci * NFR + t1];
            float xp1 = (t1 < w - 1) ? tm[ci * NFR + t1 + 1] : 0.f;
            a0 += wm * xm0 + wc * x00 + wq * x01;
            a1 += wm * x00 + wc * x01 + wq * xp1;
        }
        float y0 = leaky(r0 + a0);
        float y1 = leaky(r1 + a1);
        g_cbufA[(i * FD + co) * NFR + t] = fmaxf(y0, y1);
    }
}

// Input-side GRU gates: GI[dir][s][g] = b_ih + w_ih . [seg_feat|lab|hl_feat]
__global__ void k_gi(const float* __restrict__ w_ih, const float* __restrict__ b_ih) {
    int s = blockIdx.x; if (s >= g_S) return;
    int dir = blockIdx.y;
    __shared__ float rin[3 * FD];
    int tid = threadIdx.x;
    if (tid < 2 * FD) rin[tid] = g_hl[s * 2 * FD + tid];
    else {
        int c = tid - 2 * FD;
        rin[tid] = (g_cbufA[(0 * FD + c) * NFR] + g_cbufA[(1 * FD + c) * NFR] +
                    g_cbufA[(2 * FD + c) * NFR]) * (1.f / 3.f);
    }
    __syncthreads();
    const float* wr = w_ih + (size_t)(dir * 192 + tid) * 192;
    float acc = b_ih[dir * 192 + tid];
#pragma unroll 8
    for (int j = 0; j < 192; j++) acc += wr[j] * rin[j];
    g_gi[(dir * NACT + s) * 192 + tid] = acc;
}

// Bidirectional GRU: 2 blocks (fwd/bwd), recurrent weights in registers.
__global__ void k_gru(const float* __restrict__ w_hh, const float* __restrict__ b_hh) {
    int dir = blockIdx.x;
    int tid = threadIdx.x;
    int S = g_S;
    __shared__ float h[FD];
    __shared__ float gh[192];
    float wreg[FD];
#pragma unroll
    for (int j = 0; j < FD; j++) wreg[j] = w_hh[(size_t)(dir * 192 + tid) * FD + j];
    float bh = b_hh[dir * 192 + tid];
    if (tid < FD) h[tid] = 0.f;
    __syncthreads();
    for (int t = 0; t < S; t++) {
        int s = (dir == 0) ? t : (S - 1 - t);
        float a0 = 0.f, a1 = 0.f, a2 = 0.f, a3 = 0.f;
#pragma unroll
        for (int j = 0; j < FD; j += 4) {
            a0 += wreg[j] * h[j];
            a1 += wreg[j + 1] * h[j + 1];
            a2 += wreg[j + 2] * h[j + 2];
            a3 += wreg[j + 3] * h[j + 3];
        }
        gh[tid] = bh + (a0 + a1) + (a2 + a3);
        __syncthreads();
        if (tid < FD) {
            const float* gi = g_gi + (size_t)(dir * NACT + s) * 192;
            float r = sigm(gi[tid] + gh[tid]);
            float z = sigm(gi[FD + tid] + gh[FD + tid]);
            float n = tanhf(gi[2 * FD + tid] + r * gh[2 * FD + tid]);
            float hn = (1.f - z) * n + z * h[tid];
            h[tid] = hn;
            g_h[s * 2 * FD + dir * FD + tid] = hn;
        }
        __syncthreads();
    }
}

// Output projection -> refine_pred (also to d_out).
__global__ void k_out(const float* __restrict__ out_w, const float* __restrict__ out_b,
                      float* __restrict__ dout) {
    int s = blockIdx.x; if (s >= g_S) return;
    int a = threadIdx.x;
    __shared__ float hs[2 * FD];
    if (a < FD) { hs[a] = g_h[s * 2 * FD + a]; hs[FD + a] = g_h[s * 2 * FD + FD + a]; }
    __syncthreads();
    if (a < NACT) {
        const float* wr = out_w + a * 2 * FD;
        float acc = out_b[a];
#pragma unroll
        for (int j = 0; j < 2 * FD; j++) acc += wr[j] * hs[j];
        g_rp[s * NACT + a] = acc;
        dout[s * NACT + a] = acc;
    }
}

// rollout[a][l] = refine_pred[seg(l)][a]
__global__ void k_rollout(const int* __restrict__ aidx, float* __restrict__ dout, int L, int S) {
    __shared__ float rp_s[NACT * NACT];
    for (int idx = threadIdx.x; idx < S * NACT; idx += 128) rp_s[idx] = g_rp[idx];
    __syncthreads();
    int l = blockIdx.x * 128 + threadIdx.x;
    if (l >= L) return;
    int s = g_val2seg[aidx[l]];
    float* base = dout + (size_t)S * NACT;
#pragma unroll
    for (int a = 0; a < NACT; a++) base[(size_t)a * L + l] = rp_s[s * NACT + a];
}

// ---------------- launch ----------------
extern "C" void kernel_launch(void* const* d_in, const int* in_sizes, int n_in,
                              void* d_out, int out_size) {
    const int*   aidx = (const int*)d_in[0];
    const float* X    = (const float*)d_in[1];
    const float* Wk   = (const float*)d_in[2];
    const float* Wv   = (const float*)d_in[3];
    const float* qemb = (const float*)d_in[4];
    const float* lemb = (const float*)d_in[5];
    const float* c0w  = (const float*)d_in[6];
    const float* c0b  = (const float*)d_in[7];
    const float* bw1  = (const float*)d_in[8];
    const float* bb1  = (const float*)d_in[9];
    const float* bw2  = (const float*)d_in[10];
    const float* bb2  = (const float*)d_in[11];
    const float* wih  = (const float*)d_in[12];
    const float* whh  = (const float*)d_in[13];
    const float* bih  = (const float*)d_in[14];
    const float* bhh  = (const float*)d_in[15];
    const float* ow   = (const float*)d_in[16];
    const float* ob   = (const float*)d_in[17];
    float* out = (float*)d_out;
    int L = in_sizes[0];
    int S = (out_size - NACT * L) / NACT;

    k_init<<<1, 64>>>(aidx, L);
    k_qk<<<dim3(IND / 256, NACT), 256>>>(Wk, qemb);
    k_score<<<dim3((L + 255) / 256, SCHUNK), 256>>>(X, aidx, L);
    k_softmax<<<NACT, 256>>>(L);
    k_xsum<<<dim3(IND / 32, NACT), 256>>>(X, L);
    k_segfeat<<<NACT, 256>>>(Wv, lemb);
    k_conv0<<<dim3(FD, NSMP), 32>>>(c0w, c0b);
    int w = NFR;
    for (int lvl = 0; lvl < NBLK; lvl++) {
        k_convA<<<dim3(FD, NSMP), 32>>>(bw1, bb1, lvl, w);
        k_convB<<<dim3(FD, NSMP), 32>>>(bw2, bb2, lvl, w);
        w >>= 1;
    }
    k_gi<<<dim3(NACT, 2), 192>>>(wih, bih);
    k_gru<<<2, 192>>>(whh, bhh);
    k_out<<<NACT, 64>>>(ow, ob, out);
    k_rollout<<<(L + 127) / 128, 128>>>(aidx, out, L, S);
}

// round 15
// speedup vs baseline: 3.1917x; 1.0082x over previous
#include <cuda_runtime.h>
#include <cuda_bf16.h>
#include <stdint.h>
#include <math.h>

#define MAXL   20000
#define NACT   48
#define FD     64
#define IND    2048
#define NFR    32
#define NSMP   3
#define NBLK   5
#define SCHUNK 8

// ---------------- scratch (device globals; no allocation) ----------------
__device__ float g_spart[SCHUNK * MAXL];    // partial scores per d-chunk
__device__ float g_w[MAXL];                 // softmax weights
__device__ int   g_S;
__device__ int   g_start[NACT], g_len[NACT], g_pred[NACT], g_val2seg[NACT];
__device__ int   g_samp[NSMP * NFR];
__device__ float g_qk[NACT * IND];          // (Wk^T q_pred[s]) / 8
__device__ float g_xsum[NACT * IND];        // sum_l w_l x_l per segment
__device__ float g_hl[NACT * 2 * FD];       // [seg_feat | label_emb]
__device__ float g_cbufA[NSMP * FD * NFR];  // conv ping
__device__ float g_cbufB[NSMP * FD * NFR];  // conv pong
__device__ float g_gi[2 * NACT * 3 * FD];   // input-side GRU gates
__device__ float g_h[NACT * 2 * FD];        // [h_fwd | h_bwd]
__device__ float g_rp[NACT * NACT];         // refine_pred

// ---------------- helpers ----------------
__device__ __forceinline__ float warpSum(float v) {
#pragma unroll
    for (int o = 16; o; o >>= 1) v += __shfl_xor_sync(0xffffffffu, v, o);
    return v;
}
__device__ __forceinline__ float warpMax(float v) {
#pragma unroll
    for (int o = 16; o; o >>= 1) v = fmaxf(v, __shfl_xor_sync(0xffffffffu, v, o));
    return v;
}
__device__ __forceinline__ float leaky(float x) { return x >= 0.f ? x : 0.1f * x; }
__device__ __forceinline__ float sigm(float x)  { return 1.f / (1.f + expf(-x)); }
__device__ __forceinline__ uint32_t rotl32(uint32_t x, int r) { return (x << r) | (x >> (32 - r)); }

// Threefry-2x32-20 (jax-exact)
__device__ uint2 tf2x32(uint32_t k0, uint32_t k1, uint32_t x0, uint32_t x1) {
    uint32_t ks2 = k0 ^ k1 ^ 0x1BD11BDAu;
    x0 += k0; x1 += k1;
    x0 += x1; x1 = rotl32(x1, 13); x1 ^= x0;
    x0 += x1; x1 = rotl32(x1, 15); x1 ^= x0;
    x0 += x1; x1 = rotl32(x1, 26); x1 ^= x0;
    x0 += x1; x1 = rotl32(x1, 6);  x1 ^= x0;
    x0 += k1; x1 += ks2 + 1u;
    x0 += x1; x1 = rotl32(x1, 17); x1 ^= x0;
    x0 += x1; x1 = rotl32(x1, 29); x1 ^= x0;
    x0 += x1; x1 = rotl32(x1, 16); x1 ^= x0;
    x0 += x1; x1 = rotl32(x1, 24); x1 ^= x0;
    x0 += ks2; x1 += k0 + 2u;
    x0 += x1; x1 = rotl32(x1, 13); x1 ^= x0;
    x0 += x1; x1 = rotl32(x1, 15); x1 ^= x0;
    x0 += x1; x1 = rotl32(x1, 26); x1 ^= x0;
    x0 += x1; x1 = rotl32(x1, 6);  x1 ^= x0;
    x0 += k0; x1 += k1 + 3u;
    x0 += x1; x1 = rotl32(x1, 17); x1 ^= x0;
    x0 += x1; x1 = rotl32(x1, 29); x1 ^= x0;
    x0 += x1; x1 = rotl32(x1, 16); x1 ^= x0;
    x0 += x1; x1 = rotl32(x1, 24); x1 ^= x0;
    x0 += k1; x1 += ks2 + 4u;
    x0 += x1; x1 = rotl32(x1, 13); x1 ^= x0;
    x0 += x1; x1 = rotl32(x1, 15); x1 ^= x0;
    x0 += x1; x1 = rotl32(x1, 26); x1 ^= x0;
    x0 += x1; x1 = rotl32(x1, 6);  x1 ^= x0;
    x0 += ks2; x1 += k0 + 5u;
    return make_uint2(x0, x1);
}

// ---------------- kernels ----------------

// No-op: shifts the ncu fixed profiling slot onto k_score (launch #4).
__global__ void k_nop() {}

// Segments (sorted action_idx) + jax-PRNG sample indices, one tiny block.
__global__ void k_init(const int* __restrict__ a, int L) {
    __shared__ int lo_s[NACT + 1];
    __shared__ int S_s;
    __shared__ uint32_t bits[NACT];
    __shared__ int sel[NACT];
    __shared__ uint32_t sk0, sk1;
    int tid = threadIdx.x;
    if (tid <= NACT) {
        int lo = 0, hi = L;
        while (lo < hi) { int mid = (lo + hi) >> 1; if (a[mid] < tid) lo = mid + 1; else hi = mid; }
        lo_s[tid] = lo;
    }
    __syncthreads();
    if (tid == 0) {
        int s = 0;
        for (int vv = 0; vv < NACT; vv++) {
            int st = lo_s[vv], en = lo_s[vv + 1];
            if (en > st) { g_val2seg[vv] = s; g_start[s] = st; g_len[s] = en - st; g_pred[s] = vv; s++; }
            else g_val2seg[vv] = 0;
        }
        g_S = s; S_s = s;
    }
    __syncthreads();
    int S = S_s;
    for (int i = 0; i < NSMP; i++) {
        if (tid == 0) {
            uint2 fk  = tf2x32(0u, 42u, 0u, (uint32_t)i);   // fold_in(key(42), i)
            uint2 sub = tf2x32(fk.x, fk.y, 0u, 1u);          // split -> subkey
            sk0 = sub.x; sk1 = sub.y;
        }
        __syncthreads();
        if (tid < S) {
            uint2 o = tf2x32(sk0, sk1, 0u, (uint32_t)tid);   // partitionable random_bits
            bits[tid] = o.x ^ o.y;
        }
        __syncthreads();
        if (tid < S) {
            uint32_t kj = bits[tid];
            int rank = 0;
            for (int m = 0; m < S; m++) {
                uint32_t km = bits[m];
                rank += ((km < kj) || (km == kj && m < tid)) ? 1 : 0;
            }
            sel[tid] = (rank < NFR) ? 1 : 0;
        }
        __syncthreads();
        if (tid == 0) {
            int c = 0;
            for (int j = 0; j < S && c < NFR; j++)
                if (sel[j]) g_samp[i * NFR + c++] = j;
            while (c < NFR) { g_samp[i * NFR + c] = c % (S > 0 ? S : 1); c++; }
        }
        __syncthreads();
    }
}

// qk[s][d] = (1/8) * sum_f Wk[f][d] * query_emb[pred[s]][f]
__global__ void k_qk(const float* __restrict__ Wk, const float* __restrict__ qemb) {
    int s = blockIdx.y; if (s >= g_S) return;
    int d = blockIdx.x * 256 + threadIdx.x;
    const float* q = qemb + g_pred[s] * FD;
    float acc = 0.f;
#pragma unroll
    for (int f = 0; f < FD; f++) acc += Wk[(size_t)f * IND + d] * q[f];
    g_qk[s * IND + d] = acc * 0.125f;
}

// Pass 1 over X: partial scores per d-chunk (round-3-proven shape).
__global__ void k_score(const float* __restrict__ X, const int* __restrict__ a, int L) {
    int l = blockIdx.x * 256 + threadIdx.x;
    if (l >= L) return;
    int s = g_val2seg[a[l]];
    int dbase = blockIdx.y * (IND / SCHUNK);
    const float* qr = g_qk + s * IND + dbase;
    const float* Xp = X + (size_t)dbase * L + l;
    float a0 = 0.f, a1 = 0.f, a2 = 0.f, a3 = 0.f;
    for (int d = 0; d < IND / SCHUNK; d += 4) {
        a0 += Xp[(size_t)d * L]       * qr[d];
        a1 += Xp[(size_t)(d + 1) * L] * qr[d + 1];
        a2 += Xp[(size_t)(d + 2) * L] * qr[d + 2];
        a3 += Xp[(size_t)(d + 3) * L] * qr[d + 3];
    }
    g_spart[blockIdx.y * L + l] = (a0 + a1) + (a2 + a3);
}

// Per-segment softmax over its contiguous range.
__global__ void k_softmax(int L) {
    int s = blockIdx.x; if (s >= g_S) return;
    int st = g_start[s], len = g_len[s];
    __shared__ float red[8];
    __shared__ float bmax, bsum;
    int tid = threadIdx.x, lane = tid & 31, wp = tid >> 5;
    float mx = -3e38f;
    for (int i = tid; i < len; i += 256) {
        float sc = 0.f;
#pragma unroll
        for (int c = 0; c < SCHUNK; c++) sc += g_spart[c * L + st + i];
        g_w[st + i] = sc;
        mx = fmaxf(mx, sc);
    }
    mx = warpMax(mx);
    if (lane == 0) red[wp] = mx;
    __syncthreads();
    if (tid == 0) {
        float m = red[0];
        for (int k = 1; k < 8; k++) m = fmaxf(m, red[k]);
        bmax = m;
    }
    __syncthreads();
    float m = bmax, sum = 0.f;
    for (int i = tid; i < len; i += 256) {
        float e = expf(g_w[st + i] - m);
        g_w[st + i] = e;
        sum += e;
    }
    sum = warpSum(sum);
    if (lane == 0) red[wp] = sum;
    __syncthreads();
    if (tid == 0) {
        float z = 0.f;
        for (int k = 0; k < 8; k++) z += red[k];
        bsum = z;
    }
    __syncthreads();
    float inv = 1.f / bsum;
    for (int i = tid; i < len; i += 256) g_w[st + i] *= inv;
}

// Pass 2 over X: xsum[s][d]. Round-3 grid/mapping (4 d-rows per warp),
// with a 4-accumulator unroll for MLP (the ONLY change this round).
__global__ void k_xsum(const float* __restrict__ X, int L) {
    int s = blockIdx.y; if (s >= g_S) return;
    int st = g_start[s], len = g_len[s];
    int warp = threadIdx.x >> 5, lane = threadIdx.x & 31;
#pragma unroll
    for (int r = 0; r < 4; r++) {
        int d = blockIdx.x * 32 + warp * 4 + r;
        const float* Xr = X + (size_t)d * L + st;
        const float* wr = g_w + st;
        float ac0 = 0.f, ac1 = 0.f, ac2 = 0.f, ac3 = 0.f;
        int i = lane;
        for (; i + 96 < len; i += 128) {
            ac0 += Xr[i]      * wr[i];
            ac1 += Xr[i + 32] * wr[i + 32];
            ac2 += Xr[i + 64] * wr[i + 64];
            ac3 += Xr[i + 96] * wr[i + 96];
        }
        for (; i < len; i += 32) ac0 += Xr[i] * wr[i];
        float acc = warpSum((ac0 + ac1) + (ac2 + ac3));
        if (lane == 0) g_xsum[s * IND + d] = acc;
    }
}

// seg_feat[s][f] = Wv[f] . xsum[s]; build hl_inp = [seg_feat | label_emb].
__global__ void k_segfeat(const float* __restrict__ Wv, const float* __restrict__ lemb) {
    int s = blockIdx.x; if (s >= g_S) return;
    int warp = threadIdx.x >> 5, lane = threadIdx.x & 31;
#pragma unroll
    for (int r = 0; r < 8; r++) {
        int f = warp * 8 + r;
        const float* Wr = Wv + (size_t)f * IND;
        const float* xr = g_xsum + s * IND;
        float acc = 0.f;
        for (int dd = lane; dd < IND; dd += 32) acc += Wr[dd] * xr[dd];
        acc = warpSum(acc);
        if (lane == 0) {
            g_hl[s * 2 * FD + f] = acc;
            g_hl[s * 2 * FD + FD + f] = lemb[g_pred[s] * FD + f];
        }
    }
}

// conv0: gathered samples [128ch,32t] -> 64ch, k=3 SAME.
__global__ void k_conv0(const float* __restrict__ w0, const float* __restrict__ b0) {
    __shared__ float in_s[128 * NFR];
    int i = blockIdx.y, co = blockIdx.x, t = threadIdx.x;
    for (int idx = t; idx < 128 * NFR; idx += 32) {
        int ci = idx >> 5, tt = idx & 31;
        in_s[ci * NFR + tt] = g_hl[g_samp[i * NFR + tt] * 128 + ci];
    }
    __syncthreads();
    float acc = b0[co];
    for (int ci = 0; ci < 128; ci++) {
        const float* wp = w0 + (co * 128 + ci) * 3;
        float xm = (t > 0) ? in_s[ci * NFR + t - 1] : 0.f;
        float x0 = in_s[ci * NFR + t];
        float xp = (t < NFR - 1) ? in_s[ci * NFR + t + 1] : 0.f;
        acc += wp[0] * xm + wp[1] * x0 + wp[2] * xp;
    }
    g_cbufA[(i * FD + co) * NFR + t] = acc;
}

// level conv #1: leaky(conv(in)) -> cbufB
__global__ void k_convA(const float* __restrict__ w1, const float* __restrict__ b1, int lvl, int w) {
    __shared__ float in_s[FD * NFR];
    int i = blockIdx.y, co = blockIdx.x, t = threadIdx.x;
    for (int idx = t; idx < FD * w; idx += 32) {
        int ci = idx / w, tt = idx - ci * w;
        in_s[ci * NFR + tt] = g_cbufA[(i * FD + ci) * NFR + tt];
    }
    __syncthreads();
    if (t < w) {
        const float* wp = w1 + (size_t)(lvl * FD + co) * FD * 3;
        float acc = b1[lvl * FD + co];
        for (int ci = 0; ci < FD; ci++) {
            float xm = (t > 0) ? in_s[ci * NFR + t - 1] : 0.f;
            float x0 = in_s[ci * NFR + t];
            float xp = (t < w - 1) ? in_s[ci * NFR + t + 1] : 0.f;
            acc += wp[ci * 3] * xm + wp[ci * 3 + 1] * x0 + wp[ci * 3 + 2] * xp;
        }
        g_cbufB[(i * FD + co) * NFR + t] = leaky(acc);
    }
}

// level conv #2 + residual + leaky + maxpool/2 -> cbufA
__global__ void k_convB(const float* __restrict__ w2, const float* __restrict__ b2, int lvl, int w) {
    __shared__ float tm[FD * NFR];
    int i = blockIdx.y, co = blockIdx.x, t = threadIdx.x;
    for (int idx = t; idx < FD * w; idx += 32) {
        int ci = idx / w, tt = idx - ci * w;
        tm[ci * NFR + tt] = g_cbufB[(i * FD + ci) * NFR + tt];
    }
    int wo = w >> 1;
    float r0 = 0.f, r1 = 0.f;
    if (t < wo) {
        r0 = g_cbufA[(i * FD + co) * NFR + 2 * t];
        r1 = g_cbufA[(i * FD + co) * NFR + 2 * t + 1];
    }
    __syncthreads();
    if (t < wo) {
        const float* wp = w2 + (size_t)(lvl * FD + co) * FD * 3;
        float b = b2[lvl * FD + co];
        float a0 = b, a1 = b;
        int t0 = 2 * t, t1 = 2 * t + 1;
        for (int ci = 0; ci < FD; ci++) {
            float wm = wp[ci * 3], wc = wp[ci * 3 + 1], wq = wp[ci * 3 + 2];
            float xm0 = (t0 > 0) ? tm[ci * NFR + t0 - 1] : 0.f;
            float x00 = tm[ci * NFR + t0];
            float x01 = tm[ci * NFR + t1];
            float xp1 = (t1 < w - 1) ? tm[ci * NFR + t1 + 1] : 0.f;
            a0 += wm * xm0 + wc * x00 + wq * x01;
            a1 += wm * x00 + wc * x01 + wq * xp1;
        }
        float y0 = leaky(r0 + a0);
        float y1 = leaky(r1 + a1);
        g_cbufA[(i * FD + co) * NFR + t] = fmaxf(y0, y1);
    }
}

// Input-side GRU gates: GI[dir][s][g] = b_ih + w_ih . [seg_feat|lab|hl_feat]
__global__ void k_gi(const float* __restrict__ w_ih, const float* __restrict__ b_ih) {
    int s = blockIdx.x; if (s >= g_S) return;
    int dir = blockIdx.y;
    __shared__ float rin[3 * FD];
    int tid = threadIdx.x;
    if (tid < 2 * FD) rin[tid] = g_hl[s * 2 * FD + tid];
    else {
        int c = tid - 2 * FD;
        rin[tid] = (g_cbufA[(0 * FD + c) * NFR] + g_cbufA[(1 * FD + c) * NFR] +
                    g_cbufA[(2 * FD + c) * NFR]) * (1.f / 3.f);
    }
    __syncthreads();
    const float* wr = w_ih + (size_t)(dir * 192 + tid) * 192;
    float acc = b_ih[dir * 192 + tid];
#pragma unroll 8
    for (int j = 0; j < 192; j++) acc += wr[j] * rin[j];
    g_gi[(dir * NACT + s) * 192 + tid] = acc;
}

// Bidirectional GRU: 2 blocks (fwd/bwd), recurrent weights in registers.
__global__ void k_gru(const float* __restrict__ w_hh, const float* __restrict__ b_hh) {
    int dir = blockIdx.x;
    int tid = threadIdx.x;
    int S = g_S;
    __shared__ float h[FD];
    __shared__ float gh[192];
    float wreg[FD];
#pragma unroll
    for (int j = 0; j < FD; j++) wreg[j] = w_hh[(size_t)(dir * 192 + tid) * FD + j];
    float bh = b_hh[dir * 192 + tid];
    if (tid < FD) h[tid] = 0.f;
    __syncthreads();
    for (int t = 0; t < S; t++) {
        int s = (dir == 0) ? t : (S - 1 - t);
        float a0 = 0.f, a1 = 0.f, a2 = 0.f, a3 = 0.f;
#pragma unroll
        for (int j = 0; j < FD; j += 4) {
            a0 += wreg[j] * h[j];
            a1 += wreg[j + 1] * h[j + 1];
            a2 += wreg[j + 2] * h[j + 2];
            a3 += wreg[j + 3] * h[j + 3];
        }
        gh[tid] = bh + (a0 + a1) + (a2 + a3);
        __syncthreads();
        if (tid < FD) {
            const float* gi = g_gi + (size_t)(dir * NACT + s) * 192;
            float r = sigm(gi[tid] + gh[tid]);
            float z = sigm(gi[FD + tid] + gh[FD + tid]);
            float n = tanhf(gi[2 * FD + tid] + r * gh[2 * FD + tid]);
            float hn = (1.f - z) * n + z * h[tid];
            h[tid] = hn;
            g_h[s * 2 * FD + dir * FD + tid] = hn;
        }
        __syncthreads();
    }
}

// Output projection -> refine_pred (also to d_out).
__global__ void k_out(const float* __restrict__ out_w, const float* __restrict__ out_b,
                      float* __restrict__ dout) {
    int s = blockIdx.x; if (s >= g_S) return;
    int a = threadIdx.x;
    __shared__ float hs[2 * FD];
    if (a < FD) { hs[a] = g_h[s * 2 * FD + a]; hs[FD + a] = g_h[s * 2 * FD + FD + a]; }
    __syncthreads();
    if (a < NACT) {
        const float* wr = out_w + a * 2 * FD;
        float acc = out_b[a];
#pragma unroll
        for (int j = 0; j < 2 * FD; j++) acc += wr[j] * hs[j];
        g_rp[s * NACT + a] = acc;
        dout[s * NACT + a] = acc;
    }
}

// rollout[a][l] = refine_pred[seg(l)][a]
__global__ void k_rollout(const int* __restrict__ aidx, float* __restrict__ dout, int L, int S) {
    __shared__ float rp_s[NACT * NACT];
    for (int idx = threadIdx.x; idx < S * NACT; idx += 128) rp_s[idx] = g_rp[idx];
    __syncthreads();
    int l = blockIdx.x * 128 + threadIdx.x;
    if (l >= L) return;
    int s = g_val2seg[aidx[l]];
    float* base = dout + (size_t)S * NACT;
#pragma unroll
    for (int a = 0; a < NACT; a++) base[(size_t)a * L + l] = rp_s[s * NACT + a];
}

// ---------------- launch ----------------
extern "C" void kernel_launch(void* const* d_in, const int* in_sizes, int n_in,
                              void* d_out, int out_size) {
    const int*   aidx = (const int*)d_in[0];
    const float* X    = (const float*)d_in[1];
    const float* Wk   = (const float*)d_in[2];
    const float* Wv   = (const float*)d_in[3];
    const float* qemb = (const float*)d_in[4];
    const float* lemb = (const float*)d_in[5];
    const float* c0w  = (const float*)d_in[6];
    const float* c0b  = (const float*)d_in[7];
    const float* bw1  = (const float*)d_in[8];
    const float* bb1  = (const float*)d_in[9];
    const float* bw2  = (const float*)d_in[10];
    const float* bb2  = (const float*)d_in[11];
    const float* wih  = (const float*)d_in[12];
    const float* whh  = (const float*)d_in[13];
    const float* bih  = (const float*)d_in[14];
    const float* bhh  = (const float*)d_in[15];
    const float* ow   = (const float*)d_in[16];
    const float* ob   = (const float*)d_in[17];
    float* out = (float*)d_out;
    int L = in_sizes[0];
    int S = (out_size - NACT * L) / NACT;

    k_nop<<<1, 32>>>();                       // shifts ncu slot onto k_score
    k_init<<<1, 64>>>(aidx, L);
    k_qk<<<dim3(IND / 256, NACT), 256>>>(Wk, qemb);
    k_score<<<dim3((L + 255) / 256, SCHUNK), 256>>>(X, aidx, L);
    k_softmax<<<NACT, 256>>>(L);
    k_xsum<<<dim3(IND / 32, NACT), 256>>>(X, L);
    k_segfeat<<<NACT, 256>>>(Wv, lemb);
    k_conv0<<<dim3(FD, NSMP), 32>>>(c0w, c0b);
    int w = NFR;
    for (int lvl = 0; lvl < NBLK; lvl++) {
        k_convA<<<dim3(FD, NSMP), 32>>>(bw1, bb1, lvl, w);
        k_convB<<<dim3(FD, NSMP), 32>>>(bw2, bb2, lvl, w);
        w >>= 1;
    }
    k_gi<<<dim3(NACT, 2), 192>>>(wih, bih);
    k_gru<<<2, 192>>>(whh, bhh);
    k_out<<<NACT, 64>>>(ow, ob, out);
    k_rollout<<<(L + 127) / 128, 128>>>(aidx, out, L, S);
}